// round 1
// baseline (speedup 1.0000x reference)
#include <cuda_runtime.h>
#include <math.h>

#define NT 256                 // threads per block, 1 matrix per thread
#define MPB NT                 // matrices per block
#define FLOATS_PB (MPB * 9)    // 2304 floats
#define F4_PB (FLOATS_PB / 4)  // 576 float4 per block
#define JITTER 1e-6f
#define NSWEEPS 5

// FMA-pipe rsqrt: bit hack + 3 Newton iterations (~1e-7 rel err). Avoids MUFU
// (rt_SMSP=8 would make 30M MUFU ops the chip bottleneck at ~220us).
__device__ __forceinline__ float rsqrt_nr3(float x) {
    x = fmaxf(x, 1e-30f);
    float y = __uint_as_float(0x5f3759dfu - (__float_as_uint(x) >> 1));
    y = y * (1.5f - 0.5f * x * y * y);
    y = y * (1.5f - 0.5f * x * y * y);
    y = y * (1.5f - 0.5f * x * y * y);
    return y;
}

// One approximate-Givens Jacobi rotation on plane (p,q) of symmetric A,
// accumulating into eigenvector columns vp, vq. Division-free (McAdams).
__device__ __forceinline__ void jrot(float& app, float& aqq, float& apq,
                                     float& apr, float& aqr,
                                     float vp[3], float vq[3]) {
    float ch = 2.0f * (app - aqq);
    float sh = apq;
    bool ok = (5.828427124746190f * sh * sh) < (ch * ch);
    float w = rsqrt_nr3(ch * ch + sh * sh);
    ch = ok ? w * ch : 0.9238795325112867f;   // cos(pi/8)
    sh = ok ? w * sh : 0.3826834323650898f;   // sin(pi/8)
    float c = ch * ch - sh * sh;
    float s = 2.0f * ch * sh;
    float c2 = c * c, s2 = s * s, cs = c * s;
    float t_pp = c2 * app + 2.0f * cs * apq + s2 * aqq;
    float t_qq = s2 * app - 2.0f * cs * apq + c2 * aqq;
    float t_pq = cs * (aqq - app) + (c2 - s2) * apq;
    float t_pr = c * apr + s * aqr;
    float t_qr = c * aqr - s * apr;
    app = t_pp; aqq = t_qq; apq = t_pq; apr = t_pr; aqr = t_qr;
#pragma unroll
    for (int i = 0; i < 3; i++) {
        float a = vp[i], d = vq[i];
        vp[i] = c * a + s * d;
        vq[i] = c * d - s * a;
    }
}

__device__ __forceinline__ void cross3(const float a[3], const float b[3], float o[3]) {
    o[0] = a[1] * b[2] - a[2] * b[1];
    o[1] = a[2] * b[0] - a[0] * b[2];
    o[2] = a[0] * b[1] - a[1] * b[0];
}

__global__ void __launch_bounds__(NT)
orientation_bfn_kernel(const float* __restrict__ Rc,
                       const float* __restrict__ tarr,
                       const float* __restrict__ nz,
                       const float* __restrict__ ep,
                       float* __restrict__ out,
                       int Lmats) {
    __shared__ float4 s4[F4_PB];
    float* sf = reinterpret_cast<float*>(s4);

    const int tid = threadIdx.x;
    const long long base = (long long)blockIdx.x * FLOATS_PB;  // float offset
    const int m0 = blockIdx.x * MPB;

    // All MPB=256 matrices in a block share one t (Lmats % 256 == 0 here).
    const float tval = tarr[m0 / Lmats];
    const float stval = sqrtf(tval);

    // Fused coalesced staging: F = t*R + sqrt(t)*noise + JITTER*eps, into SMEM.
    const float4* r4 = reinterpret_cast<const float4*>(Rc + base);
    const float4* n4 = reinterpret_cast<const float4*>(nz + base);
    const float4* e4 = reinterpret_cast<const float4*>(ep + base);
#pragma unroll
    for (int i = tid; i < F4_PB; i += NT) {
        float4 a = r4[i], b = n4[i], c = e4[i];
        float4 f;
        f.x = fmaf(tval, a.x, fmaf(stval, b.x, JITTER * c.x));
        f.y = fmaf(tval, a.y, fmaf(stval, b.y, JITTER * c.y));
        f.z = fmaf(tval, a.z, fmaf(stval, b.z, JITTER * c.z));
        f.w = fmaf(tval, a.w, fmaf(stval, b.w, JITTER * c.w));
        s4[i] = f;
    }
    __syncthreads();

    // Per-thread read of its 3x3 F (stride 9, coprime with 32 -> conflict-free).
    float F[9];
#pragma unroll
    for (int k = 0; k < 9; k++) F[k] = sf[tid * 9 + k];
    __syncthreads();  // allow SMEM reuse for output

    // A = F^T F (symmetric, 6 entries)
    float a00 = F[0]*F[0] + F[3]*F[3] + F[6]*F[6];
    float a01 = F[0]*F[1] + F[3]*F[4] + F[6]*F[7];
    float a02 = F[0]*F[2] + F[3]*F[5] + F[6]*F[8];
    float a11 = F[1]*F[1] + F[4]*F[4] + F[7]*F[7];
    float a12 = F[1]*F[2] + F[4]*F[5] + F[7]*F[8];
    float a22 = F[2]*F[2] + F[5]*F[5] + F[8]*F[8];

    float V0[3] = {1.f, 0.f, 0.f};
    float V1[3] = {0.f, 1.f, 0.f};
    float V2[3] = {0.f, 0.f, 1.f};

#pragma unroll
    for (int sw = 0; sw < NSWEEPS; sw++) {
        jrot(a00, a11, a01, a02, a12, V0, V1);  // plane (0,1), r=2
        jrot(a00, a22, a02, a01, a12, V0, V2);  // plane (0,2), r=1
        jrot(a11, a22, a12, a01, a02, V1, V2);  // plane (1,2), r=0
    }

    // Sort eigenpairs descending (3 compare-swaps).
#pragma unroll
    for (int pass = 0; pass < 1; pass++) {
        if (a00 < a11) {
            float d = a00; a00 = a11; a11 = d;
#pragma unroll
            for (int i = 0; i < 3; i++) { float x = V0[i]; V0[i] = V1[i]; V1[i] = x; }
        }
        if (a00 < a22) {
            float d = a00; a00 = a22; a22 = d;
#pragma unroll
            for (int i = 0; i < 3; i++) { float x = V0[i]; V0[i] = V2[i]; V2[i] = x; }
        }
        if (a11 < a22) {
            float d = a11; a11 = a22; a22 = d;
#pragma unroll
            for (int i = 0; i < 3; i++) { float x = V1[i]; V1[i] = V2[i]; V2[i] = x; }
        }
    }

    // Force right-handed V: v3 = v1 x v2  => det(V) = +1.
    cross3(V0, V1, V2);

    // b_i = F v_i for the two dominant directions.
    float b1[3], b2[3];
#pragma unroll
    for (int i = 0; i < 3; i++) {
        b1[i] = F[3*i + 0] * V0[0] + F[3*i + 1] * V0[1] + F[3*i + 2] * V0[2];
        b2[i] = F[3*i + 0] * V1[0] + F[3*i + 1] * V1[1] + F[3*i + 2] * V1[2];
    }

    float u1[3], u2[3], u3[3];
    float inv1 = rsqrt_nr3(b1[0]*b1[0] + b1[1]*b1[1] + b1[2]*b1[2]);
#pragma unroll
    for (int i = 0; i < 3; i++) u1[i] = b1[i] * inv1;

    float proj = u1[0]*b2[0] + u1[1]*b2[1] + u1[2]*b2[2];
#pragma unroll
    for (int i = 0; i < 3; i++) b2[i] -= proj * u1[i];
    float inv2 = rsqrt_nr3(b2[0]*b2[0] + b2[1]*b2[1] + b2[2]*b2[2]);
#pragma unroll
    for (int i = 0; i < 3; i++) u2[i] = b2[i] * inv2;

    cross3(u1, u2, u3);  // det(U) = +1; sign flip on smallest sigma is implicit

    // R = U V^T  (the SO(3) projection, matches reference incl. det correction)
#pragma unroll
    for (int i = 0; i < 3; i++) {
#pragma unroll
        for (int j = 0; j < 3; j++) {
            sf[tid * 9 + 3*i + j] = u1[i] * V0[j] + u2[i] * V1[j] + u3[i] * V2[j];
        }
    }
    __syncthreads();

    // Coalesced float4 store of results.
    float4* o4 = reinterpret_cast<float4*>(out + base);
#pragma unroll
    for (int i = tid; i < F4_PB; i += NT) o4[i] = s4[i];
}

extern "C" void kernel_launch(void* const* d_in, const int* in_sizes, int n_in,
                              void* d_out, int out_size) {
    const float* Rc = (const float*)d_in[0];   // R_clean  (N*L*9)
    const float* t  = (const float*)d_in[1];   // t        (N)
    const float* nz = (const float*)d_in[2];   // noise    (N*L*9)
    const float* ep = (const float*)d_in[3];   // eps_noise(N*L*9)
    float* out = (float*)d_out;

    const int total = in_sizes[0];
    const int mats = total / 9;
    const int N = in_sizes[1];
    const int Lmats = mats / N;
    const int blocks = mats / MPB;  // 8192 for N=256, L=8192

    orientation_bfn_kernel<<<blocks, NT>>>(Rc, t, nz, ep, out, Lmats);
}

// round 3
// speedup vs baseline: 1.1109x; 1.1109x over previous
#include <cuda_runtime.h>
#include <math.h>

#define NT 256                 // threads per block, 1 matrix per thread
#define MPB NT                 // matrices per block
#define FLOATS_PB (MPB * 9)    // 2304 floats
#define F4_PB (FLOATS_PB / 4)  // 576 float4 per block
#define JITTER 1e-6f
#define NSWEEPS 4

// FMA-pipe rsqrt, quake seed + N Newton steps.
// Seed err ~3.4e-2; 1 step ~1.75e-3; 2 steps ~4.6e-6; 3 steps fp32-exact.
// Avoids MUFU (rt_SMSP=8 would bottleneck the chip at ~30M rsqrts).
template <int STEPS>
__device__ __forceinline__ float rsqrt_nr(float x) {
    x = fmaxf(x, 1e-30f);
    float y = __uint_as_float(0x5f3759dfu - (__float_as_uint(x) >> 1));
#pragma unroll
    for (int i = 0; i < STEPS; i++)
        y = y * fmaf(-0.5f * x, y * y, 1.5f);
    return y;
}

// One approximate-Givens Jacobi rotation on plane (p,q) of symmetric A,
// accumulating into eigenvector columns vp, vq. Division-free (McAdams).
// Needs 2 Newton steps: 1-step leaves 1.75e-3 scale error per rotation,
// which compounds to ~4e-2 over 12 rotations (measured in R2).
__device__ __forceinline__ void jrot(float& app, float& aqq, float& apq,
                                     float& apr, float& aqr,
                                     float vp[3], float vq[3]) {
    float ch = 2.0f * (app - aqq);
    float sh = apq;
    bool ok = (5.828427124746190f * sh * sh) < (ch * ch);
    float w = rsqrt_nr<2>(ch * ch + sh * sh);
    ch = ok ? w * ch : 0.9238795325112867f;   // cos(pi/8)
    sh = ok ? w * sh : 0.3826834323650898f;   // sin(pi/8)
    float c = ch * ch - sh * sh;
    float s = 2.0f * ch * sh;
    float c2 = c * c, s2 = s * s, cs = c * s;
    float t_pp = fmaf(c2, app, fmaf(2.0f * cs, apq, s2 * aqq));
    float t_qq = (app + aqq) - t_pp;                 // trace preservation
    float t_pq = fmaf(cs, (aqq - app), (c2 - s2) * apq);
    float t_pr = fmaf(c, apr, s * aqr);
    float t_qr = fmaf(c, aqr, -s * apr);
    app = t_pp; aqq = t_qq; apq = t_pq; apr = t_pr; aqr = t_qr;
#pragma unroll
    for (int i = 0; i < 3; i++) {
        float a = vp[i], d = vq[i];
        vp[i] = fmaf(c, a, s * d);
        vq[i] = fmaf(c, d, -s * a);
    }
}

__device__ __forceinline__ void cross3(const float a[3], const float b[3], float o[3]) {
    o[0] = fmaf(a[1], b[2], -a[2] * b[1]);
    o[1] = fmaf(a[2], b[0], -a[0] * b[2]);
    o[2] = fmaf(a[0], b[1], -a[1] * b[0]);
}

__global__ void __launch_bounds__(NT)
orientation_bfn_kernel(const float* __restrict__ Rc,
                       const float* __restrict__ tarr,
                       const float* __restrict__ nz,
                       const float* __restrict__ ep,
                       float* __restrict__ out,
                       int Lmats) {
    __shared__ float4 s4[F4_PB];
    float* sf = reinterpret_cast<float*>(s4);

    const int tid = threadIdx.x;
    const long long base = (long long)blockIdx.x * FLOATS_PB;  // float offset
    const int m0 = blockIdx.x * MPB;

    // All MPB=256 matrices in a block share one t (Lmats % 256 == 0 here).
    const float tval = tarr[m0 / Lmats];
    const float stval = sqrtf(tval);

    // Fused coalesced staging: F = t*R + sqrt(t)*noise + JITTER*eps, into SMEM.
    const float4* r4 = reinterpret_cast<const float4*>(Rc + base);
    const float4* n4 = reinterpret_cast<const float4*>(nz + base);
    const float4* e4 = reinterpret_cast<const float4*>(ep + base);
#pragma unroll
    for (int i = tid; i < F4_PB; i += NT) {
        float4 a = r4[i], b = n4[i], c = e4[i];
        float4 f;
        f.x = fmaf(tval, a.x, fmaf(stval, b.x, JITTER * c.x));
        f.y = fmaf(tval, a.y, fmaf(stval, b.y, JITTER * c.y));
        f.z = fmaf(tval, a.z, fmaf(stval, b.z, JITTER * c.z));
        f.w = fmaf(tval, a.w, fmaf(stval, b.w, JITTER * c.w));
        s4[i] = f;
    }
    __syncthreads();

    // Per-thread read of its 3x3 F (stride 9, coprime with 32 -> conflict-free).
    float F[9];
#pragma unroll
    for (int k = 0; k < 9; k++) F[k] = sf[tid * 9 + k];
    __syncthreads();  // allow SMEM reuse for output

    // A = F^T F (symmetric, 6 entries)
    float a00 = F[0]*F[0] + F[3]*F[3] + F[6]*F[6];
    float a01 = F[0]*F[1] + F[3]*F[4] + F[6]*F[7];
    float a02 = F[0]*F[2] + F[3]*F[5] + F[6]*F[8];
    float a11 = F[1]*F[1] + F[4]*F[4] + F[7]*F[7];
    float a12 = F[1]*F[2] + F[4]*F[5] + F[7]*F[8];
    float a22 = F[2]*F[2] + F[5]*F[5] + F[8]*F[8];

    float V0[3] = {1.f, 0.f, 0.f};
    float V1[3] = {0.f, 1.f, 0.f};
    float V2[3] = {0.f, 0.f, 1.f};

#pragma unroll
    for (int sw = 0; sw < NSWEEPS; sw++) {
        jrot(a00, a11, a01, a02, a12, V0, V1);  // plane (0,1)
        jrot(a00, a22, a02, a01, a12, V0, V2);  // plane (0,2)
        jrot(a11, a22, a12, a01, a02, V1, V2);  // plane (1,2)
    }

    // Sort eigenpairs descending (3 compare-swaps).
    if (a00 < a11) {
        float d = a00; a00 = a11; a11 = d;
#pragma unroll
        for (int i = 0; i < 3; i++) { float x = V0[i]; V0[i] = V1[i]; V1[i] = x; }
    }
    if (a00 < a22) {
        float d = a00; a00 = a22; a22 = d;
#pragma unroll
        for (int i = 0; i < 3; i++) { float x = V0[i]; V0[i] = V2[i]; V2[i] = x; }
    }
    if (a11 < a22) {
        float d = a11; a11 = a22; a22 = d;
#pragma unroll
        for (int i = 0; i < 3; i++) { float x = V1[i]; V1[i] = V2[i]; V2[i] = x; }
    }

    // Force right-handed V: v3 = v1 x v2  => det(V) = +1.
    cross3(V0, V1, V2);

    // b_i = F v_i for the two dominant directions.
    float b1[3], b2[3];
#pragma unroll
    for (int i = 0; i < 3; i++) {
        b1[i] = fmaf(F[3*i + 0], V0[0], fmaf(F[3*i + 1], V0[1], F[3*i + 2] * V0[2]));
        b2[i] = fmaf(F[3*i + 0], V1[0], fmaf(F[3*i + 1], V1[1], F[3*i + 2] * V1[2]));
    }

    float u1[3], u2[3], u3[3];
    float inv1 = rsqrt_nr<2>(b1[0]*b1[0] + b1[1]*b1[1] + b1[2]*b1[2]);
#pragma unroll
    for (int i = 0; i < 3; i++) u1[i] = b1[i] * inv1;

    float proj = fmaf(u1[0], b2[0], fmaf(u1[1], b2[1], u1[2] * b2[2]));
#pragma unroll
    for (int i = 0; i < 3; i++) b2[i] = fmaf(-proj, u1[i], b2[i]);
    float inv2 = rsqrt_nr<2>(b2[0]*b2[0] + b2[1]*b2[1] + b2[2]*b2[2]);
#pragma unroll
    for (int i = 0; i < 3; i++) u2[i] = b2[i] * inv2;

    cross3(u1, u2, u3);  // det(U) = +1; sign flip on smallest sigma is implicit

    // R = U V^T  (the SO(3) projection, matches reference incl. det correction)
#pragma unroll
    for (int i = 0; i < 3; i++) {
#pragma unroll
        for (int j = 0; j < 3; j++) {
            sf[tid * 9 + 3*i + j] =
                fmaf(u1[i], V0[j], fmaf(u2[i], V1[j], u3[i] * V2[j]));
        }
    }
    __syncthreads();

    // Coalesced float4 store of results.
    float4* o4 = reinterpret_cast<float4*>(out + base);
#pragma unroll
    for (int i = tid; i < F4_PB; i += NT) o4[i] = s4[i];
}

extern "C" void kernel_launch(void* const* d_in, const int* in_sizes, int n_in,
                              void* d_out, int out_size) {
    const float* Rc = (const float*)d_in[0];   // R_clean  (N*L*9)
    const float* t  = (const float*)d_in[1];   // t        (N)
    const float* nz = (const float*)d_in[2];   // noise    (N*L*9)
    const float* ep = (const float*)d_in[3];   // eps_noise(N*L*9)
    float* out = (float*)d_out;

    const int total = in_sizes[0];
    const int mats = total / 9;
    const int N = in_sizes[1];
    const int Lmats = mats / N;
    const int blocks = mats / MPB;  // 8192 for N=256, L=8192

    orientation_bfn_kernel<<<blocks, NT>>>(Rc, t, nz, ep, out, Lmats);
}

// round 4
// speedup vs baseline: 1.1986x; 1.0789x over previous
#include <cuda_runtime.h>
#include <math.h>

#define NT 256                 // threads per block, 1 matrix per thread
#define MPB NT                 // matrices per block
#define FLOATS_PB (MPB * 9)    // 2304 floats
#define F4_PB (FLOATS_PB / 4)  // 576 float4 per block
#define JITTER 1e-6f
#define NSWEEPS 3              // EXACT Givens: quadratic convergence, 3 sweeps ample

// FMA-pipe rsqrt, quake seed + N Newton steps.
// Seed err ~3.4e-2; 1 step ~1.75e-3; 2 steps ~4.6e-6; 3 steps fp32-exact.
// Avoids MUFU (rt_SMSP=8 would bottleneck the chip at ~30M rsqrts).
template <int STEPS>
__device__ __forceinline__ float rsqrt_nr(float x) {
    x = fmaxf(x, 1e-30f);
    float y = __uint_as_float(0x5f3759dfu - (__float_as_uint(x) >> 1));
#pragma unroll
    for (int i = 0; i < STEPS; i++)
        y = y * fmaf(-0.5f * x, y * y, 1.5f);
    return y;
}

// EXACT annihilating Givens rotation on plane (p,q), division-free.
//   d = app-aqq, r = sqrt(d^2 + 4 apq^2)
//   cos2t = |d|/r, sin2t = sign(d)*2*apq/r  (zeroes a'pq for any quadrant)
//   u = (1+cos2t)/2 >= 0.5  -> c = sqrt(u), s = sin2t/(2c)
// Both rsqrts are on the FMA pipe. a'pq is exactly 0 -> set analytically.
__device__ __forceinline__ void jrot(float& app, float& aqq, float& apq,
                                     float& apr, float& aqr,
                                     float vp[3], float vq[3]) {
    float d  = app - aqq;
    float r2 = fmaf(d, d, 4.0f * apq * apq);
    float w  = rsqrt_nr<2>(r2);
    float cos2t = fabsf(d) * w;
    float sin2t = 2.0f * apq * copysignf(w, d);
    float u     = fmaf(0.5f, cos2t, 0.5f);          // in [0.5, 1]
    float invc  = rsqrt_nr<2>(u);
    float c = u * invc;                              // sqrt(u)
    float s = 0.5f * sin2t * invc;
    // Degenerate plane (d ~ 0 and apq ~ 0): identity rotation.
    bool tiny = (r2 < 1e-24f);
    c = tiny ? 1.0f : c;
    s = tiny ? 0.0f : s;

    float c2 = c * c, s2 = s * s, cs = c * s;
    float t_pp = fmaf(c2, app, fmaf(2.0f * cs, apq, s2 * aqq));
    float t_qq = (app + aqq) - t_pp;                 // trace preservation
    float t_pr = fmaf(c, apr, s * aqr);
    float t_qr = fmaf(c, aqr, -s * apr);
    app = t_pp; aqq = t_qq; apq = 0.0f; apr = t_pr; aqr = t_qr;
#pragma unroll
    for (int i = 0; i < 3; i++) {
        float a = vp[i], b = vq[i];
        vp[i] = fmaf(c, a, s * b);
        vq[i] = fmaf(c, b, -s * a);
    }
}

__device__ __forceinline__ void cross3(const float a[3], const float b[3], float o[3]) {
    o[0] = fmaf(a[1], b[2], -a[2] * b[1]);
    o[1] = fmaf(a[2], b[0], -a[0] * b[2]);
    o[2] = fmaf(a[0], b[1], -a[1] * b[0]);
}

__global__ void __launch_bounds__(NT)
orientation_bfn_kernel(const float* __restrict__ Rc,
                       const float* __restrict__ tarr,
                       const float* __restrict__ nz,
                       const float* __restrict__ ep,
                       float* __restrict__ out,
                       int Lmats) {
    __shared__ float4 s4[F4_PB];
    float* sf = reinterpret_cast<float*>(s4);

    const int tid = threadIdx.x;
    const long long base = (long long)blockIdx.x * FLOATS_PB;  // float offset
    const int m0 = blockIdx.x * MPB;

    // All MPB=256 matrices in a block share one t (Lmats % 256 == 0 here).
    const float tval = tarr[m0 / Lmats];
    const float stval = sqrtf(tval);

    // Fused coalesced staging: F = t*R + sqrt(t)*noise + JITTER*eps, into SMEM.
    const float4* r4 = reinterpret_cast<const float4*>(Rc + base);
    const float4* n4 = reinterpret_cast<const float4*>(nz + base);
    const float4* e4 = reinterpret_cast<const float4*>(ep + base);
#pragma unroll
    for (int i = tid; i < F4_PB; i += NT) {
        float4 a = r4[i], b = n4[i], c = e4[i];
        float4 f;
        f.x = fmaf(tval, a.x, fmaf(stval, b.x, JITTER * c.x));
        f.y = fmaf(tval, a.y, fmaf(stval, b.y, JITTER * c.y));
        f.z = fmaf(tval, a.z, fmaf(stval, b.z, JITTER * c.z));
        f.w = fmaf(tval, a.w, fmaf(stval, b.w, JITTER * c.w));
        s4[i] = f;
    }
    __syncthreads();

    // Per-thread read of its 3x3 F (stride 9, coprime with 32 -> conflict-free).
    float F[9];
#pragma unroll
    for (int k = 0; k < 9; k++) F[k] = sf[tid * 9 + k];
    __syncthreads();  // allow SMEM reuse for output

    // A = F^T F (symmetric, 6 entries)
    float a00 = F[0]*F[0] + F[3]*F[3] + F[6]*F[6];
    float a01 = F[0]*F[1] + F[3]*F[4] + F[6]*F[7];
    float a02 = F[0]*F[2] + F[3]*F[5] + F[6]*F[8];
    float a11 = F[1]*F[1] + F[4]*F[4] + F[7]*F[7];
    float a12 = F[1]*F[2] + F[4]*F[5] + F[7]*F[8];
    float a22 = F[2]*F[2] + F[5]*F[5] + F[8]*F[8];

    float V0[3] = {1.f, 0.f, 0.f};
    float V1[3] = {0.f, 1.f, 0.f};
    float V2[3] = {0.f, 0.f, 1.f};

#pragma unroll
    for (int sw = 0; sw < NSWEEPS; sw++) {
        jrot(a00, a11, a01, a02, a12, V0, V1);  // plane (0,1)
        jrot(a00, a22, a02, a01, a12, V0, V2);  // plane (0,2)
        jrot(a11, a22, a12, a01, a02, V1, V2);  // plane (1,2)
    }

    // Sort eigenpairs descending (3 compare-swaps).
    if (a00 < a11) {
        float d = a00; a00 = a11; a11 = d;
#pragma unroll
        for (int i = 0; i < 3; i++) { float x = V0[i]; V0[i] = V1[i]; V1[i] = x; }
    }
    if (a00 < a22) {
        float d = a00; a00 = a22; a22 = d;
#pragma unroll
        for (int i = 0; i < 3; i++) { float x = V0[i]; V0[i] = V2[i]; V2[i] = x; }
    }
    if (a11 < a22) {
        float d = a11; a11 = a22; a22 = d;
#pragma unroll
        for (int i = 0; i < 3; i++) { float x = V1[i]; V1[i] = V2[i]; V2[i] = x; }
    }

    // Force right-handed V: v3 = v1 x v2  => det(V) = +1.
    cross3(V0, V1, V2);

    // b_i = F v_i for the two dominant directions.
    float b1[3], b2[3];
#pragma unroll
    for (int i = 0; i < 3; i++) {
        b1[i] = fmaf(F[3*i + 0], V0[0], fmaf(F[3*i + 1], V0[1], F[3*i + 2] * V0[2]));
        b2[i] = fmaf(F[3*i + 0], V1[0], fmaf(F[3*i + 1], V1[1], F[3*i + 2] * V1[2]));
    }

    float u1[3], u2[3], u3[3];
    float inv1 = rsqrt_nr<2>(b1[0]*b1[0] + b1[1]*b1[1] + b1[2]*b1[2]);
#pragma unroll
    for (int i = 0; i < 3; i++) u1[i] = b1[i] * inv1;

    float proj = fmaf(u1[0], b2[0], fmaf(u1[1], b2[1], u1[2] * b2[2]));
#pragma unroll
    for (int i = 0; i < 3; i++) b2[i] = fmaf(-proj, u1[i], b2[i]);
    float inv2 = rsqrt_nr<2>(b2[0]*b2[0] + b2[1]*b2[1] + b2[2]*b2[2]);
#pragma unroll
    for (int i = 0; i < 3; i++) u2[i] = b2[i] * inv2;

    cross3(u1, u2, u3);  // det(U) = +1; sign flip on smallest sigma is implicit

    // R = U V^T  (the SO(3) projection, matches reference incl. det correction)
#pragma unroll
    for (int i = 0; i < 3; i++) {
#pragma unroll
        for (int j = 0; j < 3; j++) {
            sf[tid * 9 + 3*i + j] =
                fmaf(u1[i], V0[j], fmaf(u2[i], V1[j], u3[i] * V2[j]));
        }
    }
    __syncthreads();

    // Coalesced float4 store of results.
    float4* o4 = reinterpret_cast<float4*>(out + base);
#pragma unroll
    for (int i = tid; i < F4_PB; i += NT) o4[i] = s4[i];
}

extern "C" void kernel_launch(void* const* d_in, const int* in_sizes, int n_in,
                              void* d_out, int out_size) {
    const float* Rc = (const float*)d_in[0];   // R_clean  (N*L*9)
    const float* t  = (const float*)d_in[1];   // t        (N)
    const float* nz = (const float*)d_in[2];   // noise    (N*L*9)
    const float* ep = (const float*)d_in[3];   // eps_noise(N*L*9)
    float* out = (float*)d_out;

    const int total = in_sizes[0];
    const int mats = total / 9;
    const int N = in_sizes[1];
    const int Lmats = mats / N;
    const int blocks = mats / MPB;  // 8192 for N=256, L=8192

    orientation_bfn_kernel<<<blocks, NT>>>(Rc, t, nz, ep, out, Lmats);
}